// round 11
// baseline (speedup 1.0000x reference)
#include <cuda_runtime.h>
#include <cuda_bf16.h>

#define NB 8
#define NC 256
#define LIN 2046
#define LP 2048
#define IC 64
#define CQ 8
#define OCH 128
#define NSPLIT 32
#define MSPLIT 4

// ---------------- scratch ----------------
__device__ float g_y [2*NB*IC*LP];       // conv partial (in-half 0)
__device__ float g_y2[2*NB*IC*LP];       // conv partial (in-half 1)
__device__ float g_feat[2*NB*IC*LP];
__device__ float g_bnps[2][512];
__device__ float g_bnpq[2][512];
__device__ float g_qt[NB*LP*CQ];
__device__ float g_kt[NB*LP*CQ];
__device__ __nv_bfloat16 g_vtb[NB*IC*LP];            // V transposed [b][c][m], bf16
__device__ __nv_bfloat16 g_pamaccb[MSPLIT*NB*LP*IC]; // partial acc [z][b][l][ch], bf16
__device__ float g_pamS[MSPLIT*NB*LP];
__device__ float g_safeat[NB*IC*LP];
__device__ float g_scfeat[NB*IC*LP];
__device__ float g_epart[NB*NSPLIT*IC*IC];
__device__ float g_attnT[NB*IC*IC];
__device__ float g_conv[2*NB*IC*LP];
__device__ float g_cm[NB*IC];

// ---------------- fp32x2 helpers ----------------
__device__ __forceinline__ unsigned long long pk2(float a, float b){
    unsigned long long r; asm("mov.b64 %0, {%1, %2};" : "=l"(r) : "f"(a), "f"(b)); return r;
}
__device__ __forceinline__ float2 upk2(unsigned long long a){
    float2 r; asm("mov.b64 {%0, %1}, %2;" : "=f"(r.x), "=f"(r.y) : "l"(a)); return r;
}
__device__ __forceinline__ unsigned long long ffma2(unsigned long long a, unsigned long long b, unsigned long long c){
    unsigned long long d; asm("fma.rn.f32x2 %0, %1, %2, %3;" : "=l"(d) : "l"(a), "l"(b), "l"(c)); return d;
}
__device__ __forceinline__ unsigned long long fmul2(unsigned long long a, unsigned long long b){
    unsigned long long d; asm("mul.rn.f32x2 %0, %1, %2;" : "=l"(d) : "l"(a), "l"(b)); return d;
}
__device__ __forceinline__ unsigned smem_u32(const void* p){
    unsigned r; asm("{ .reg .u64 t; cvta.to.shared.u64 t, %1; cvt.u32.u64 %0, t; }" : "=r"(r) : "l"(p)); return r;
}
__device__ __forceinline__ void ldmx4(unsigned &r0, unsigned &r1, unsigned &r2, unsigned &r3, unsigned addr){
    asm volatile("ldmatrix.sync.aligned.m8n8.x4.shared.b16 {%0,%1,%2,%3}, [%4];"
        : "=r"(r0),"=r"(r1),"=r"(r2),"=r"(r3) : "r"(addr));
}
__device__ __forceinline__ void mma16816(float &d0,float &d1,float &d2,float &d3,
        unsigned a0,unsigned a1,unsigned a2,unsigned a3,unsigned b0,unsigned b1){
    asm volatile("mma.sync.aligned.m16n8k16.row.col.f32.bf16.bf16.f32 "
        "{%0,%1,%2,%3}, {%4,%5,%6,%7}, {%8,%9}, {%0,%1,%2,%3};"
        : "+f"(d0),"+f"(d1),"+f"(d2),"+f"(d3)
        : "r"(a0),"r"(a1),"r"(a2),"r"(a3),"r"(b0),"r"(b1));
}
__device__ __forceinline__ unsigned cvtbf2(float hi, float lo){
    unsigned r; asm("cvt.rn.bf16x2.f32 %0, %1, %2;" : "=r"(r) : "f"(hi), "f"(lo)); return r;
}

// ---------------- conv1x1: both branches fused; z=(ih,oh); also zeroes g_cm ----------------
__global__ __launch_bounds__(256) void k_conv1(const float* __restrict__ x,
        const float* __restrict__ W5a, const float* __restrict__ W5c){
    int t = threadIdx.x;
    int lt = blockIdx.x*256 + t;
    int b = blockIdx.y;
    int z = blockIdx.z; int ih = z >> 1, oh = z & 1;
    if(blockIdx.x == 0 && z == 0 && t < 64) g_cm[b*64 + t] = 0.f;
    __shared__ __align__(16) float wsa[64][36];
    __shared__ __align__(16) float wsc[64][36];
    unsigned long long accA[16], accC[16];
    #pragma unroll
    for(int i=0;i<16;i++){ accA[i]=0ull; accC[i]=0ull; }
    bool valid = (lt>=1 && lt<=LIN);
    int lsrc = lt-1;
    for(int ci=0; ci<2; ci++){
        int cc = ih*2 + ci;
        __syncthreads();
        for(int idx=t; idx<64*32; idx+=256){
            int c = idx & 63, o = idx >> 6;
            wsa[c][o] = W5a[(oh*32+o)*256 + cc*64 + c];
            wsc[c][o] = W5c[(oh*32+o)*256 + cc*64 + c];
        }
        __syncthreads();
        if(valid){
            #pragma unroll 4
            for(int c=0;c<64;c++){
                float xv = x[(b*NC + cc*64 + c)*LIN + lsrc];
                unsigned long long xx = pk2(xv,xv);
                #pragma unroll
                for(int j=0;j<8;j++){
                    ulonglong2 wa = *reinterpret_cast<const ulonglong2*>(&wsa[c][4*j]);
                    accA[2*j]   = ffma2(xx, wa.x, accA[2*j]);
                    accA[2*j+1] = ffma2(xx, wa.y, accA[2*j+1]);
                }
                #pragma unroll
                for(int j=0;j<8;j++){
                    ulonglong2 wc = *reinterpret_cast<const ulonglong2*>(&wsc[c][4*j]);
                    accC[2*j]   = ffma2(xx, wc.x, accC[2*j]);
                    accC[2*j+1] = ffma2(xx, wc.y, accC[2*j+1]);
                }
            }
        }
    }
    float* base = (ih ? g_y2 : g_y);
    float* outA = base + (0*NB + b)*IC*LP;
    float* outC = base + (1*NB + b)*IC*LP;
    #pragma unroll
    for(int j=0;j<16;j++){
        float2 pa = upk2(accA[j]);
        outA[(oh*32+2*j)*LP   + lt] = pa.x;
        outA[(oh*32+2*j+1)*LP + lt] = pa.y;
    }
    #pragma unroll
    for(int j=0;j<16;j++){
        float2 pc = upk2(accC[j]);
        outC[(oh*32+2*j)*LP   + lt] = pc.x;
        outC[(oh*32+2*j+1)*LP + lt] = pc.y;
    }
}

// ---------------- BN stats partials (dual buffer sum) ----------------
__global__ __launch_bounds__(256) void k_bnstats(int sel){
    int ch = blockIdx.x & 63, br = blockIdx.x >> 6;
    int sl = blockIdx.y;
    int t = threadIdx.x;
    float s=0.f, sq=0.f;
    for(int bb=0;bb<2;bb++){
        int b = sl*2+bb;
        const float4* p  = reinterpret_cast<const float4*>(&g_y [((br*NB+b)*IC + ch)*LP]);
        const float4* p2 = reinterpret_cast<const float4*>(&g_y2[((br*NB+b)*IC + ch)*LP]);
        for(int i=t;i<LP/4;i+=256){
            float4 v = p[i], w = p2[i];
            v.x+=w.x; v.y+=w.y; v.z+=w.z; v.w+=w.w;
            s  += v.x+v.y+v.z+v.w;
            sq += v.x*v.x + v.y*v.y + v.z*v.z + v.w*v.w;
        }
    }
    __shared__ float rs[256], rq[256];
    rs[t]=s; rq[t]=sq; __syncthreads();
    for(int off=128;off;off>>=1){
        if(t<off){ rs[t]+=rs[t+off]; rq[t]+=rq[t+off]; }
        __syncthreads();
    }
    if(t==0){
        g_bnps[sel][(br*64+ch)*4+sl] = rs[0];
        g_bnpq[sel][(br*64+ch)*4+sl] = rq[0];
    }
}

// ---------------- BN apply + ReLU (+fused colmean when sel=1) ----------------
__global__ __launch_bounds__(256) void k_bnapply(int sel, const float* __restrict__ g0, const float* __restrict__ be0,
                          const float* __restrict__ g1, const float* __restrict__ be1){
    float* out = sel ? g_conv : g_feat;
    int i4 = blockIdx.x*blockDim.x + threadIdx.x;
    int t = threadIdx.x;
    int flat = i4*4;
    int ch = (flat >> 11) & 63;
    int b  = (flat >> 17) & 7;
    int br = flat >> 20;
    float s=0.f, sq=0.f;
    #pragma unroll
    for(int sl=0;sl<4;sl++){
        s  += g_bnps[sel][(br*64+ch)*4+sl];
        sq += g_bnpq[sel][(br*64+ch)*4+sl];
    }
    const float inv = 1.0f/(NB*LP);
    float mean = s*inv;
    float var  = sq*inv - mean*mean;
    float rstd = rsqrtf(var + 1e-5f);
    float gm = br ? g1[ch] : g0[ch];
    float be = br ? be1[ch] : be0[ch];
    float sc = rstd*gm, sh = be - mean*sc;
    float4 v = reinterpret_cast<const float4*>(g_y)[i4];
    float4 w = reinterpret_cast<const float4*>(g_y2)[i4];
    v.x = fmaxf((v.x+w.x)*sc+sh, 0.f);
    v.y = fmaxf((v.y+w.y)*sc+sh, 0.f);
    v.z = fmaxf((v.z+w.z)*sc+sh, 0.f);
    v.w = fmaxf((v.w+w.w)*sc+sh, 0.f);
    reinterpret_cast<float4*>(out)[i4] = v;
    if(sel){
        __shared__ float rsum[256];
        rsum[t] = v.x+v.y+v.z+v.w;
        __syncthreads();
        for(int off=128;off;off>>=1){
            if(t<off) rsum[t]+=rsum[t+off];
            __syncthreads();
        }
        if(t==0) atomicAdd(&g_cm[b*IC+ch], rsum[0]);
    }
}

// ---------------- Stage A: qkv (0..127) + CAM energy (128..383) ----------------
__global__ __launch_bounds__(256) void k_stageA(const float* __restrict__ Wq, const float* __restrict__ bq,
        const float* __restrict__ Wk, const float* __restrict__ bk,
        const float* __restrict__ Wv, const float* __restrict__ bv){
    int t = threadIdx.x;
    int sub = blockIdx.x;
    __shared__ __align__(16) float ws[64][52];
    __shared__ float fsm[64][65];
    if(sub < 128){
        int zz = sub >> 6;
        int rem = sub & 63; int b = rem >> 3, lc = rem & 7;
        int l = lc*256 + t;
        const float* f1 = &g_feat[b*IC*LP];
        if(zz == 0){
            // q(8) + k(8) + v[0:16]
            for(int idx=t; idx<64*32; idx+=256){
                int c = idx & 63, o = idx >> 6;
                float v;
                if(o<8)       v = Wq[o*64+c];
                else if(o<16) v = Wk[(o-8)*64+c];
                else          v = Wv[(o-16)*64+c];
                ws[c][o] = v;
            }
            __syncthreads();
            unsigned long long acc[16];
            #pragma unroll
            for(int i=0;i<16;i++) acc[i]=0ull;
            #pragma unroll 8
            for(int c=0;c<64;c++){
                float fv = f1[c*LP + l];
                unsigned long long xx = pk2(fv,fv);
                #pragma unroll
                for(int j=0;j<8;j++){
                    ulonglong2 w2 = *reinterpret_cast<const ulonglong2*>(&ws[c][4*j]);
                    acc[2*j]   = ffma2(xx, w2.x, acc[2*j]);
                    acc[2*j+1] = ffma2(xx, w2.y, acc[2*j+1]);
                }
            }
            float* qp = &g_qt[(b*LP+l)*CQ];
            float* kp = &g_kt[(b*LP+l)*CQ];
            #pragma unroll
            for(int j=0;j<4;j++){
                float2 p = upk2(acc[j]);
                qp[2*j]   = p.x + bq[2*j];
                qp[2*j+1] = p.y + bq[2*j+1];
            }
            #pragma unroll
            for(int j=4;j<8;j++){
                float2 p = upk2(acc[j]);
                kp[2*(j-4)]   = p.x + bk[2*(j-4)];
                kp[2*(j-4)+1] = p.y + bk[2*(j-4)+1];
            }
            #pragma unroll
            for(int j=8;j<16;j++){
                float2 p = upk2(acc[j]);
                int c = 2*(j-8);
                g_vtb[(b*IC + c)*LP + l]   = __float2bfloat16(p.x + bv[c]);
                g_vtb[(b*IC + c+1)*LP + l] = __float2bfloat16(p.y + bv[c+1]);
            }
        } else {
            // v[16:64] = 48 outs
            for(int idx=t; idx<64*48; idx+=256){
                int c = idx & 63, o = idx >> 6;
                ws[c][o] = Wv[(16+o)*64 + c];
            }
            __syncthreads();
            unsigned long long acc[24];
            #pragma unroll
            for(int i=0;i<24;i++) acc[i]=0ull;
            #pragma unroll 8
            for(int c=0;c<64;c++){
                float fv = f1[c*LP + l];
                unsigned long long xx = pk2(fv,fv);
                #pragma unroll
                for(int j=0;j<12;j++){
                    ulonglong2 w2 = *reinterpret_cast<const ulonglong2*>(&ws[c][4*j]);
                    acc[2*j]   = ffma2(xx, w2.x, acc[2*j]);
                    acc[2*j+1] = ffma2(xx, w2.y, acc[2*j+1]);
                }
            }
            #pragma unroll
            for(int j=0;j<24;j++){
                float2 p = upk2(acc[j]);
                int c = 16 + 2*j;
                g_vtb[(b*IC + c)*LP + l]   = __float2bfloat16(p.x + bv[c]);
                g_vtb[(b*IC + c+1)*LP + l] = __float2bfloat16(p.y + bv[c+1]);
            }
        }
    } else {
        // CAM energy
        int e = sub - 128; int b = e >> 5, ls = e & 31;
        int d = t & 63, cw = t >> 6;
        float acc[16];
        #pragma unroll
        for(int i=0;i<16;i++) acc[i]=0.f;
        const float* f2 = &g_feat[(NB + b)*IC*LP];
        int l0 = ls*(LP/NSPLIT);
        for(int idx=t; idx<64*64; idx+=256){
            int c = idx >> 6, ll = idx & 63;
            fsm[c][ll] = f2[c*LP + l0 + ll];
        }
        __syncthreads();
        for(int ll=0; ll<64; ll++){
            float fd = fsm[d][ll];
            #pragma unroll
            for(int i=0;i<16;i++) acc[i] += fsm[cw*16+i][ll]*fd;
        }
        float* ep = &g_epart[((b*NSPLIT+ls)*IC)*IC];
        #pragma unroll
        for(int i=0;i<16;i++) ep[(cw*16+i)*IC + d] = acc[i];
    }
}

// ---------------- Stage B: PAM tensor-core (0..511) + CAM softmax (512..639) ----------------
__global__ __launch_bounds__(256) void k_stageB(){
    int t = threadIdx.x;
    int sub = blockIdx.x;
    __shared__ __align__(16) float ksm[64*8];                 // K tile [64 m][8]
    __shared__ __align__(16) __nv_bfloat16 vsmT[64][72];      // V tile [c][m], 144B rows
    __shared__ __align__(16) __nv_bfloat16 Psm[128][72];      // P tile [l][m], 144B rows
    __shared__ float Ssm[256];
    if(sub < 512){
        int z = sub >> 7;
        int rem = sub & 127; int b = rem >> 4, lc = rem & 15;
        int lane = t & 31, w = t >> 5;
        int mh = t >> 7, lloc = t & 127;      // score-phase mapping
        int lglob = lc*128 + lloc;
        const ulonglong2* qg = reinterpret_cast<const ulonglong2*>(&g_qt[(b*LP+lglob)*CQ]);
        ulonglong2 qa = qg[0], qb = qg[1];
        float d[8][4];
        #pragma unroll
        for(int i=0;i<8;i++){ d[i][0]=0.f; d[i][1]=0.f; d[i][2]=0.f; d[i][3]=0.f; }
        float Sp = 0.f;
        unsigned psb = smem_u32(Psm), vsb = smem_u32(vsmT);
        int mat = lane >> 3, mi8 = lane & 7;
        unsigned aaddr = psb + (unsigned)((w*16 + mi8 + (mat&1)*8)*144 + ((mat>>1)*8)*2);
        unsigned baddr[4];
        #pragma unroll
        for(int p=0;p<4;p++)
            baddr[p] = vsb + (unsigned)((p*16 + (mat>>1)*8 + mi8)*144 + (mat&1)*16);
        for(int mt=0; mt<8; mt++){
            int m0 = z*512 + mt*64;
            __syncthreads();
            if(t < 128){
                int row = t >> 1, h = t & 1;
                *reinterpret_cast<float4*>(&ksm[row*8 + h*4]) =
                    *reinterpret_cast<const float4*>(&g_kt[(b*LP + m0 + row)*CQ + h*4]);
            }
            #pragma unroll
            for(int r=0;r<2;r++){
                int idx = t + 256*r;
                int row = idx >> 3, col8 = idx & 7;
                *reinterpret_cast<uint4*>(&vsmT[row][col8*8]) =
                    *reinterpret_cast<const uint4*>(&g_vtb[(b*IC+row)*LP + m0 + col8*8]);
            }
            __syncthreads();
            {
                unsigned pk[16];
                int mbase = mh*32;
                #pragma unroll
                for(int mi=0; mi<32; mi+=2){
                    const ulonglong2* kp = reinterpret_cast<const ulonglong2*>(&ksm[(mbase+mi)*8]);
                    ulonglong2 k0 = kp[0], k1 = kp[1];
                    ulonglong2 k2 = kp[2], k3 = kp[3];
                    unsigned long long s2 = fmul2(qa.x, k0.x);
                    s2 = ffma2(qa.y, k0.y, s2);
                    s2 = ffma2(qb.x, k1.x, s2);
                    s2 = ffma2(qb.y, k1.y, s2);
                    float2 sp0 = upk2(s2);
                    float e0 = __expf(sp0.x + sp0.y);
                    unsigned long long u2 = fmul2(qa.x, k2.x);
                    u2 = ffma2(qa.y, k2.y, u2);
                    u2 = ffma2(qb.x, k3.x, u2);
                    u2 = ffma2(qb.y, k3.y, u2);
                    float2 sp1 = upk2(u2);
                    float e1 = __expf(sp1.x + sp1.y);
                    Sp += e0 + e1;
                    pk[mi>>1] = cvtbf2(e1, e0);
                }
                uint4* pd = reinterpret_cast<uint4*>(reinterpret_cast<char*>(Psm) + lloc*144 + mh*64);
                const uint4* ps = reinterpret_cast<const uint4*>(pk);
                pd[0] = ps[0]; pd[1] = ps[1]; pd[2] = ps[2]; pd[3] = ps[3];
            }
            __syncthreads();
            #pragma unroll
            for(int ks=0; ks<4; ks++){
                unsigned a0,a1,a2,a3;
                ldmx4(a0,a1,a2,a3, aaddr + ks*32);
                #pragma unroll
                for(int p=0;p<4;p++){
                    unsigned b0,b1,b2,b3;
                    ldmx4(b0,b1,b2,b3, baddr[p] + ks*32);
                    mma16816(d[2*p][0],d[2*p][1],d[2*p][2],d[2*p][3], a0,a1,a2,a3, b0,b1);
                    mma16816(d[2*p+1][0],d[2*p+1][1],d[2*p+1][2],d[2*p+1][3], a0,a1,a2,a3, b2,b3);
                }
            }
        }
        Ssm[t] = Sp;
        __syncthreads();
        if(t < 128)
            g_pamS[(z*NB+b)*LP + lc*128 + t] = Ssm[t] + Ssm[128+t];
        // write accumulators: pamaccb[z][b][l][ch], (ch,ch+1) packed per u32
        int g = lane >> 2, tid4 = lane & 3;
        __nv_bfloat16* bb = g_pamaccb + (unsigned)((z*NB+b)*LP + lc*128 + w*16)*IC;
        #pragma unroll
        for(int nb=0; nb<8; nb++){
            int ch = nb*8 + tid4*2;
            *reinterpret_cast<unsigned*>(&bb[(unsigned)g*IC + ch])     = cvtbf2(d[nb][1], d[nb][0]);
            *reinterpret_cast<unsigned*>(&bb[(unsigned)(g+8)*IC + ch]) = cvtbf2(d[nb][3], d[nb][2]);
        }
    } else {
        int g = sub - 512;
        int rg = t >> 6, dd = t & 63;
        int row = g*4 + rg;
        int b = row >> 6, c = row & 63;
        float E = 0.f;
        #pragma unroll 8
        for(int p=0;p<NSPLIT;p++) E += g_epart[((b*NSPLIT+p)*IC + c)*IC + dd];
        int base = rg*64;
        Ssm[base+dd] = E; __syncthreads();
        for(int off=32;off;off>>=1){ if(dd<off) Ssm[base+dd] = fminf(Ssm[base+dd], Ssm[base+dd+off]); __syncthreads(); }
        float mn = Ssm[base]; __syncthreads();
        float pe = __expf(mn - E);
        Ssm[base+dd] = pe; __syncthreads();
        for(int off=32;off;off>>=1){ if(dd<off) Ssm[base+dd] += Ssm[base+dd+off]; __syncthreads(); }
        float inv = 1.f/Ssm[base];
        g_attnT[(b*IC + dd)*IC + c] = pe*inv;
    }
}

// ---------------- Stage C: PAM merge (0..63) + CAM apply (64..191) ----------------
__global__ __launch_bounds__(256) void k_stageC(const float* __restrict__ gamma_pam,
                                                const float* __restrict__ gamma_cam){
    int t = threadIdx.x;
    int sub = blockIdx.x;
    __shared__ __align__(16) float atsm[64][36];
    if(sub < 64){
        int b = sub >> 3, lc = sub & 7;
        int l = lc*256 + t;
        float S = 0.f;
        #pragma unroll
        for(int z=0;z<MSPLIT;z++) S += g_pamS[(z*NB+b)*LP + l];
        float inv = 1.0f/S;
        float gm = gamma_pam[0];
        const float* f1 = &g_feat[b*IC*LP];
        float* outp = &g_safeat[b*IC*LP];
        const uint4* pz[MSPLIT];
        #pragma unroll
        for(int z=0;z<MSPLIT;z++)
            pz[z] = reinterpret_cast<const uint4*>(g_pamaccb + (unsigned)((z*NB+b)*LP + l)*IC);
        #pragma unroll
        for(int q=0;q<8;q++){
            float sx[4], sy[4];
            #pragma unroll
            for(int r=0;r<4;r++){ sx[r]=0.f; sy[r]=0.f; }
            #pragma unroll
            for(int z=0;z<MSPLIT;z++){
                uint4 a = pz[z][q];
                unsigned ua[4] = {a.x, a.y, a.z, a.w};
                #pragma unroll
                for(int r=0;r<4;r++){
                    __nv_bfloat162 ha = *reinterpret_cast<__nv_bfloat162*>(&ua[r]);
                    sx[r] += __bfloat162float(ha.x);
                    sy[r] += __bfloat162float(ha.y);
                }
            }
            #pragma unroll
            for(int r=0;r<4;r++){
                int ch = q*8 + r*2;
                outp[ch*LP + l]     = gm*(sx[r]*inv) + f1[ch*LP + l];
                outp[(ch+1)*LP + l] = gm*(sy[r]*inv) + f1[(ch+1)*LP + l];
            }
        }
    } else {
        int e = sub - 64;
        int half = e >> 6;
        int rem = e & 63; int b = rem >> 3, lc = rem & 7;
        int l = lc*256 + t;
        for(int idx=t; idx<64*32; idx+=256){
            int d = idx >> 5, c = idx & 31;
            atsm[d][c] = g_attnT[b*4096 + d*64 + half*32 + c];
        }
        __syncthreads();
        unsigned long long acc[16];
        #pragma unroll
        for(int i=0;i<16;i++) acc[i]=0ull;
        const float* f2 = &g_feat[(NB+b)*IC*LP];
        #pragma unroll 8
        for(int d=0; d<64; d++){
            float fv = f2[d*LP + l];
            unsigned long long xx = pk2(fv, fv);
            const ulonglong2* ar = reinterpret_cast<const ulonglong2*>(&atsm[d][0]);
            #pragma unroll
            for(int j=0;j<8;j++){
                ulonglong2 a2 = ar[j];
                acc[2*j]   = ffma2(xx, a2.x, acc[2*j]);
                acc[2*j+1] = ffma2(xx, a2.y, acc[2*j+1]);
            }
        }
        float gm = gamma_cam[0];
        float* outp = &g_scfeat[b*IC*LP];
        #pragma unroll
        for(int j=0;j<16;j++){
            float2 p = upk2(acc[j]);
            int c = half*32 + 2*j;
            outp[c*LP+l]     = gm*p.x + f2[c*LP+l];
            outp[(c+1)*LP+l] = gm*p.y + f2[(c+1)*LP+l];
        }
    }
}

// ---------------- conv3: full 64 outs per block; z=(br,ih) ----------------
__global__ __launch_bounds__(256) void k_conv3(const float* __restrict__ W51, const float* __restrict__ W52){
    int t=threadIdx.x; int l0 = blockIdx.x*256; int l = l0+t; int b=blockIdx.y;
    int z=blockIdx.z; int br = z >> 1, ih = z & 1;
    const float* W  = br ? W52 : W51;
    const float* in = br ? &g_scfeat[b*IC*LP] : &g_safeat[b*IC*LP];
    __shared__ __align__(16) float insm[32][258];
    __shared__ __align__(16) float wsm[96][68];
    unsigned long long acc[32];
    #pragma unroll
    for(int i=0;i<32;i++) acc[i]=0ull;
    for(int idx=t; idx<32*258; idx+=256){
        int ic = idx/258, pos = idx - ic*258;
        int ll = l0 + pos - 1;
        insm[ic][pos] = (ll>=0 && ll<LP) ? in[(ih*32+ic)*LP + ll] : 0.f;
    }
    for(int idx=t; idx<32*3*64; idx+=256){
        int o = idx & 63; int rest = idx >> 6; int ic = rest/3, j = rest - ic*3;
        wsm[ic*3+j][o] = W[(o*IC + ih*32+ic)*3 + j];
    }
    __syncthreads();
    for(int ic=0; ic<32; ic++){
        float xv[3] = { insm[ic][t], insm[ic][t+1], insm[ic][t+2] };
        #pragma unroll
        for(int j=0;j<3;j++){
            unsigned long long xx = pk2(xv[j], xv[j]);
            const ulonglong2* wr = reinterpret_cast<const ulonglong2*>(&wsm[ic*3+j][0]);
            #pragma unroll
            for(int q=0;q<16;q++){
                ulonglong2 w2 = wr[q];
                acc[2*q]   = ffma2(xx, w2.x, acc[2*q]);
                acc[2*q+1] = ffma2(xx, w2.y, acc[2*q+1]);
            }
        }
    }
    float* out = (ih ? g_y2 : g_y) + (br*NB+b)*IC*LP;
    #pragma unroll
    for(int q=0;q<32;q++){
        float2 p = upk2(acc[q]);
        out[(2*q)*LP + l]   = p.x;
        out[(2*q+1)*LP + l] = p.y;
    }
}

// ---------------- outconv (0..255) + sasc (256) ----------------
__global__ __launch_bounds__(256) void k_outconv(const float* __restrict__ W6, const float* __restrict__ b6,
        const float* __restrict__ W7, const float* __restrict__ b7,
        const float* __restrict__ W8, const float* __restrict__ b8,
        float* __restrict__ dout){
    int t=threadIdx.x;
    int sub = blockIdx.x;
    if(sub == 256){
        __shared__ float cm[NB*IC];
        if(t < 256) { cm[t] = g_cm[t]*(1.0f/LP); cm[t+256] = g_cm[t+256]*(1.0f/LP); }
        __syncthreads();
        #pragma unroll
        for(int r=0;r<4;r++){
            int o = r*256 + t;
            int b = o >> 7, oc = o & 127;
            float s = b8[oc];
            #pragma unroll 8
            for(int ic=0; ic<64; ic++) s += W8[oc*64+ic]*cm[b*64+ic];
            dout[b*128+oc] = s;
        }
        return;
    }
    int z = sub >> 6;
    int rem = sub & 63; int b = rem >> 3, lc = rem & 7;
    int l0 = lc*256; int l = l0+t;
    int br = z >> 1, oh = z & 1;
    const float* W    = br ? W7 : W6;
    const float* bias = br ? b7 : b6;
    const float* in = &g_conv[(br*NB+b)*IC*LP];
    float* out = dout + 1024 + br*(NB*OCH*LP) + (b*OCH + oh*64)*LP;
    __shared__ __align__(16) float insm[32][256];
    __shared__ __align__(16) float wsm[32][68];
    unsigned long long acc[32];
    #pragma unroll
    for(int i=0;i<32;i++) acc[i]=0ull;
    for(int cc=0;cc<2;cc++){
        __syncthreads();
        for(int idx=t; idx<32*256; idx+=256){
            int ic = idx >> 8, ll = idx & 255;
            insm[ic][ll] = in[(cc*32+ic)*LP + l0 + ll];
        }
        for(int idx=t; idx<32*64; idx+=256){
            int ic = idx & 31, o = idx >> 5;
            wsm[ic][o] = W[(oh*64+o)*IC + cc*32 + ic];
        }
        __syncthreads();
        for(int ic=0; ic<32; ic++){
            float fv = insm[ic][t];
            unsigned long long xx = pk2(fv,fv);
            const ulonglong2* wr = reinterpret_cast<const ulonglong2*>(&wsm[ic][0]);
            #pragma unroll
            for(int q=0;q<16;q++){
                ulonglong2 w2 = wr[q];
                acc[2*q]   = ffma2(xx, w2.x, acc[2*q]);
                acc[2*q+1] = ffma2(xx, w2.y, acc[2*q+1]);
            }
        }
    }
    #pragma unroll
    for(int q=0;q<32;q++){
        float2 p = upk2(acc[q]);
        int o = 2*q;
        out[o*LP + l]     = p.x + bias[oh*64+o];
        out[(o+1)*LP + l] = p.y + bias[oh*64+o+1];
    }
}

// ---------------- launch ----------------
extern "C" void kernel_launch(void* const* d_in, const int* in_sizes, int n_in,
                              void* d_out, int out_size){
    (void)in_sizes; (void)n_in; (void)out_size;
    const float* x   = (const float*)d_in[0];
    const float* W5a = (const float*)d_in[1];
    const float* g5a = (const float*)d_in[2];
    const float* b5a = (const float*)d_in[3];
    const float* W5c = (const float*)d_in[4];
    const float* g5c = (const float*)d_in[5];
    const float* b5c = (const float*)d_in[6];
    const float* Wq  = (const float*)d_in[7];
    const float* bq  = (const float*)d_in[8];
    const float* Wk  = (const float*)d_in[9];
    const float* bk  = (const float*)d_in[10];
    const float* Wv  = (const float*)d_in[11];
    const float* bv  = (const float*)d_in[12];
    const float* gpam= (const float*)d_in[13];
    const float* gcam= (const float*)d_in[14];
    const float* W51 = (const float*)d_in[15];
    const float* g51 = (const float*)d_in[16];
    const float* b51 = (const float*)d_in[17];
    const float* W52 = (const float*)d_in[18];
    const float* g52 = (const float*)d_in[19];
    const float* b52 = (const float*)d_in[20];
    const float* W6  = (const float*)d_in[21];
    const float* b6  = (const float*)d_in[22];
    const float* W7  = (const float*)d_in[23];
    const float* b7  = (const float*)d_in[24];
    const float* W8  = (const float*)d_in[25];
    const float* b8  = (const float*)d_in[26];
    float* out = (float*)d_out;

    k_conv1<<<dim3(8,8,4),256>>>(x, W5a, W5c);
    k_bnstats<<<dim3(128,4),256>>>(0);
    k_bnapply<<<2048,256>>>(0, g5a,b5a,g5c,b5c);

    k_stageA<<<384,256>>>(Wq,bq,Wk,bk,Wv,bv);
    k_stageB<<<640,256>>>();
    k_stageC<<<192,256>>>(gpam,gcam);

    k_conv3<<<dim3(8,8,4),256>>>(W51,W52);
    k_bnstats<<<dim3(128,4),256>>>(1);
    k_bnapply<<<2048,256>>>(1, g51,b51,g52,b52);

    k_outconv<<<257,256>>>(W6,b6,W7,b7,W8,b8,out);
}

// round 12
// speedup vs baseline: 1.0270x; 1.0270x over previous
#include <cuda_runtime.h>
#include <cuda_bf16.h>

#define NB 8
#define NC 256
#define LIN 2046
#define LP 2048
#define IC 64
#define CQ 8
#define OCH 128
#define NSPLIT 32
#define MSPLIT 4

// ---------------- scratch ----------------
__device__ float g_y [2*NB*IC*LP];       // conv partial (in-half 0)
__device__ float g_y2[2*NB*IC*LP];       // conv partial (in-half 1)
__device__ float g_feat[2*NB*IC*LP];
__device__ float g_bnps[2][512];
__device__ float g_bnpq[2][512];
__device__ float g_qt[NB*LP*CQ];
__device__ float g_kt[NB*LP*CQ];
__device__ __nv_bfloat16 g_vtb[NB*IC*LP];   // V transposed [b][c][m], bf16
__device__ float g_pamacc[MSPLIT*NB*IC*LP]; // partial acc [z][b][ch][l], fp32
__device__ float g_pamS[MSPLIT*NB*LP];
__device__ float g_safeat[NB*IC*LP];
__device__ float g_scfeat[NB*IC*LP];
__device__ float g_epart[NB*NSPLIT*IC*IC];
__device__ float g_attnT[NB*IC*IC];
__device__ float g_conv[2*NB*IC*LP];
__device__ float g_cm[NB*IC];

// ---------------- fp32x2 helpers ----------------
__device__ __forceinline__ unsigned long long pk2(float a, float b){
    unsigned long long r; asm("mov.b64 %0, {%1, %2};" : "=l"(r) : "f"(a), "f"(b)); return r;
}
__device__ __forceinline__ float2 upk2(unsigned long long a){
    float2 r; asm("mov.b64 {%0, %1}, %2;" : "=f"(r.x), "=f"(r.y) : "l"(a)); return r;
}
__device__ __forceinline__ unsigned long long ffma2(unsigned long long a, unsigned long long b, unsigned long long c){
    unsigned long long d; asm("fma.rn.f32x2 %0, %1, %2, %3;" : "=l"(d) : "l"(a), "l"(b), "l"(c)); return d;
}
__device__ __forceinline__ unsigned long long fmul2(unsigned long long a, unsigned long long b){
    unsigned long long d; asm("mul.rn.f32x2 %0, %1, %2;" : "=l"(d) : "l"(a), "l"(b)); return d;
}
__device__ __forceinline__ unsigned smem_u32(const void* p){
    unsigned r; asm("{ .reg .u64 t; cvta.to.shared.u64 t, %1; cvt.u32.u64 %0, t; }" : "=r"(r) : "l"(p)); return r;
}
__device__ __forceinline__ void ldmx4(unsigned &r0, unsigned &r1, unsigned &r2, unsigned &r3, unsigned addr){
    asm volatile("ldmatrix.sync.aligned.m8n8.x4.shared.b16 {%0,%1,%2,%3}, [%4];"
        : "=r"(r0),"=r"(r1),"=r"(r2),"=r"(r3) : "r"(addr));
}
__device__ __forceinline__ void mma16816(float &d0,float &d1,float &d2,float &d3,
        unsigned a0,unsigned a1,unsigned a2,unsigned a3,unsigned b0,unsigned b1){
    asm volatile("mma.sync.aligned.m16n8k16.row.col.f32.bf16.bf16.f32 "
        "{%0,%1,%2,%3}, {%4,%5,%6,%7}, {%8,%9}, {%0,%1,%2,%3};"
        : "+f"(d0),"+f"(d1),"+f"(d2),"+f"(d3)
        : "r"(a0),"r"(a1),"r"(a2),"r"(a3),"r"(b0),"r"(b1));
}
__device__ __forceinline__ unsigned cvtbf2(float hi, float lo){
    unsigned r; asm("cvt.rn.bf16x2.f32 %0, %1, %2;" : "=r"(r) : "f"(hi), "f"(lo)); return r;
}

// ---------------- conv1x1: both branches fused; z=(ih,oh); also zeroes g_cm ----------------
__global__ __launch_bounds__(256) void k_conv1(const float* __restrict__ x,
        const float* __restrict__ W5a, const float* __restrict__ W5c){
    int t = threadIdx.x;
    int lt = blockIdx.x*256 + t;
    int b = blockIdx.y;
    int z = blockIdx.z; int ih = z >> 1, oh = z & 1;
    if(blockIdx.x == 0 && z == 0 && t < 64) g_cm[b*64 + t] = 0.f;
    __shared__ __align__(16) float wsa[64][36];
    __shared__ __align__(16) float wsc[64][36];
    unsigned long long accA[16], accC[16];
    #pragma unroll
    for(int i=0;i<16;i++){ accA[i]=0ull; accC[i]=0ull; }
    bool valid = (lt>=1 && lt<=LIN);
    int lsrc = lt-1;
    for(int ci=0; ci<2; ci++){
        int cc = ih*2 + ci;
        __syncthreads();
        for(int idx=t; idx<64*32; idx+=256){
            int c = idx & 63, o = idx >> 6;
            wsa[c][o] = W5a[(oh*32+o)*256 + cc*64 + c];
            wsc[c][o] = W5c[(oh*32+o)*256 + cc*64 + c];
        }
        __syncthreads();
        if(valid){
            #pragma unroll 4
            for(int c=0;c<64;c++){
                float xv = x[(b*NC + cc*64 + c)*LIN + lsrc];
                unsigned long long xx = pk2(xv,xv);
                #pragma unroll
                for(int j=0;j<8;j++){
                    ulonglong2 wa = *reinterpret_cast<const ulonglong2*>(&wsa[c][4*j]);
                    accA[2*j]   = ffma2(xx, wa.x, accA[2*j]);
                    accA[2*j+1] = ffma2(xx, wa.y, accA[2*j+1]);
                }
                #pragma unroll
                for(int j=0;j<8;j++){
                    ulonglong2 wc = *reinterpret_cast<const ulonglong2*>(&wsc[c][4*j]);
                    accC[2*j]   = ffma2(xx, wc.x, accC[2*j]);
                    accC[2*j+1] = ffma2(xx, wc.y, accC[2*j+1]);
                }
            }
        }
    }
    float* base = (ih ? g_y2 : g_y);
    float* outA = base + (0*NB + b)*IC*LP;
    float* outC = base + (1*NB + b)*IC*LP;
    #pragma unroll
    for(int j=0;j<16;j++){
        float2 pa = upk2(accA[j]);
        outA[(oh*32+2*j)*LP   + lt] = pa.x;
        outA[(oh*32+2*j+1)*LP + lt] = pa.y;
    }
    #pragma unroll
    for(int j=0;j<16;j++){
        float2 pc = upk2(accC[j]);
        outC[(oh*32+2*j)*LP   + lt] = pc.x;
        outC[(oh*32+2*j+1)*LP + lt] = pc.y;
    }
}

// ---------------- BN stats partials (dual buffer sum) ----------------
__global__ __launch_bounds__(256) void k_bnstats(int sel){
    int ch = blockIdx.x & 63, br = blockIdx.x >> 6;
    int sl = blockIdx.y;
    int t = threadIdx.x;
    float s=0.f, sq=0.f;
    for(int bb=0;bb<2;bb++){
        int b = sl*2+bb;
        const float4* p  = reinterpret_cast<const float4*>(&g_y [((br*NB+b)*IC + ch)*LP]);
        const float4* p2 = reinterpret_cast<const float4*>(&g_y2[((br*NB+b)*IC + ch)*LP]);
        for(int i=t;i<LP/4;i+=256){
            float4 v = p[i], w = p2[i];
            v.x+=w.x; v.y+=w.y; v.z+=w.z; v.w+=w.w;
            s  += v.x+v.y+v.z+v.w;
            sq += v.x*v.x + v.y*v.y + v.z*v.z + v.w*v.w;
        }
    }
    __shared__ float rs[256], rq[256];
    rs[t]=s; rq[t]=sq; __syncthreads();
    for(int off=128;off;off>>=1){
        if(t<off){ rs[t]+=rs[t+off]; rq[t]+=rq[t+off]; }
        __syncthreads();
    }
    if(t==0){
        g_bnps[sel][(br*64+ch)*4+sl] = rs[0];
        g_bnpq[sel][(br*64+ch)*4+sl] = rq[0];
    }
}

// ---------------- BN apply + ReLU (+fused colmean when sel=1) ----------------
__global__ __launch_bounds__(256) void k_bnapply(int sel, const float* __restrict__ g0, const float* __restrict__ be0,
                          const float* __restrict__ g1, const float* __restrict__ be1){
    float* out = sel ? g_conv : g_feat;
    int i4 = blockIdx.x*blockDim.x + threadIdx.x;
    int t = threadIdx.x;
    int flat = i4*4;
    int ch = (flat >> 11) & 63;
    int b  = (flat >> 17) & 7;
    int br = flat >> 20;
    float s=0.f, sq=0.f;
    #pragma unroll
    for(int sl=0;sl<4;sl++){
        s  += g_bnps[sel][(br*64+ch)*4+sl];
        sq += g_bnpq[sel][(br*64+ch)*4+sl];
    }
    const float inv = 1.0f/(NB*LP);
    float mean = s*inv;
    float var  = sq*inv - mean*mean;
    float rstd = rsqrtf(var + 1e-5f);
    float gm = br ? g1[ch] : g0[ch];
    float be = br ? be1[ch] : be0[ch];
    float sc = rstd*gm, sh = be - mean*sc;
    float4 v = reinterpret_cast<const float4*>(g_y)[i4];
    float4 w = reinterpret_cast<const float4*>(g_y2)[i4];
    v.x = fmaxf((v.x+w.x)*sc+sh, 0.f);
    v.y = fmaxf((v.y+w.y)*sc+sh, 0.f);
    v.z = fmaxf((v.z+w.z)*sc+sh, 0.f);
    v.w = fmaxf((v.w+w.w)*sc+sh, 0.f);
    reinterpret_cast<float4*>(out)[i4] = v;
    if(sel){
        __shared__ float rsum[256];
        rsum[t] = v.x+v.y+v.z+v.w;
        __syncthreads();
        for(int off=128;off;off>>=1){
            if(t<off) rsum[t]+=rsum[t+off];
            __syncthreads();
        }
        if(t==0) atomicAdd(&g_cm[b*IC+ch], rsum[0]);
    }
}

// ---------------- Stage A: qkv 3-way (0..191) + CAM energy (192..447) ----------------
__global__ __launch_bounds__(256) void k_stageA(const float* __restrict__ Wq, const float* __restrict__ bq,
        const float* __restrict__ Wk, const float* __restrict__ bk,
        const float* __restrict__ Wv, const float* __restrict__ bv){
    int t = threadIdx.x;
    int sub = blockIdx.x;
    __shared__ __align__(16) float ws[64][36];
    __shared__ float fsm[64][65];
    if(sub < 192){
        int zz = sub / 64;
        int rem = sub - zz*64; int b = rem >> 3, lc = rem & 7;
        int l = lc*256 + t;
        const float* f1 = &g_feat[b*IC*LP];
        if(zz == 0){
            for(int idx=t; idx<64*16; idx+=256){
                int c = idx & 63, o = idx >> 6;
                ws[c][o] = (o<8) ? Wq[o*64+c] : Wk[(o-8)*64+c];
            }
            __syncthreads();
            unsigned long long acc[8];
            #pragma unroll
            for(int i=0;i<8;i++) acc[i]=0ull;
            #pragma unroll 8
            for(int c=0;c<64;c++){
                float fv = f1[c*LP + l];
                unsigned long long xx = pk2(fv,fv);
                #pragma unroll
                for(int j=0;j<4;j++){
                    ulonglong2 w2 = *reinterpret_cast<const ulonglong2*>(&ws[c][4*j]);
                    acc[2*j]   = ffma2(xx, w2.x, acc[2*j]);
                    acc[2*j+1] = ffma2(xx, w2.y, acc[2*j+1]);
                }
            }
            float* qp = &g_qt[(b*LP+l)*CQ];
            float* kp = &g_kt[(b*LP+l)*CQ];
            #pragma unroll
            for(int j=0;j<4;j++){
                float2 p = upk2(acc[j]);
                qp[2*j]   = p.x + bq[2*j];
                qp[2*j+1] = p.y + bq[2*j+1];
            }
            #pragma unroll
            for(int j=4;j<8;j++){
                float2 p = upk2(acc[j]);
                kp[2*(j-4)]   = p.x + bk[2*(j-4)];
                kp[2*(j-4)+1] = p.y + bk[2*(j-4)+1];
            }
        } else {
            int half = zz-1;
            for(int idx=t; idx<64*32; idx+=256){
                int c = idx & 63, o = idx >> 6;
                ws[c][o] = Wv[(half*32+o)*64 + c];
            }
            __syncthreads();
            unsigned long long acc[16];
            #pragma unroll
            for(int i=0;i<16;i++) acc[i]=0ull;
            #pragma unroll 8
            for(int c=0;c<64;c++){
                float fv = f1[c*LP + l];
                unsigned long long xx = pk2(fv,fv);
                #pragma unroll
                for(int j=0;j<8;j++){
                    ulonglong2 w2 = *reinterpret_cast<const ulonglong2*>(&ws[c][4*j]);
                    acc[2*j]   = ffma2(xx, w2.x, acc[2*j]);
                    acc[2*j+1] = ffma2(xx, w2.y, acc[2*j+1]);
                }
            }
            #pragma unroll
            for(int j=0;j<16;j++){
                float2 p = upk2(acc[j]);
                int c = half*32 + 2*j;
                g_vtb[(b*IC + c)*LP + l]   = __float2bfloat16(p.x + bv[c]);
                g_vtb[(b*IC + c+1)*LP + l] = __float2bfloat16(p.y + bv[c+1]);
            }
        }
    } else {
        // CAM energy
        int e = sub - 192; int b = e >> 5, ls = e & 31;
        int d = t & 63, cw = t >> 6;
        float acc[16];
        #pragma unroll
        for(int i=0;i<16;i++) acc[i]=0.f;
        const float* f2 = &g_feat[(NB + b)*IC*LP];
        int l0 = ls*(LP/NSPLIT);
        for(int idx=t; idx<64*64; idx+=256){
            int c = idx >> 6, ll = idx & 63;
            fsm[c][ll] = f2[c*LP + l0 + ll];
        }
        __syncthreads();
        for(int ll=0; ll<64; ll++){
            float fd = fsm[d][ll];
            #pragma unroll
            for(int i=0;i<16;i++) acc[i] += fsm[cw*16+i][ll]*fd;
        }
        float* ep = &g_epart[((b*NSPLIT+ls)*IC)*IC];
        #pragma unroll
        for(int i=0;i<16;i++) ep[(cw*16+i)*IC + d] = acc[i];
    }
}

// ---------------- Stage B: PAM tensor-core (0..511) + CAM softmax (512..639) ----------------
__global__ __launch_bounds__(256) void k_stageB(){
    int t = threadIdx.x;
    int sub = blockIdx.x;
    __shared__ __align__(16) float ksm[64*8];                 // K tile [64 m][8]
    __shared__ __align__(16) __nv_bfloat16 vsmT[64][72];      // V tile [c][m], 144B rows
    __shared__ __align__(16) __nv_bfloat16 Psm[128][72];      // P tile [l][m], 144B rows
    __shared__ float Ssm[256];
    if(sub < 512){
        int z = sub >> 7;
        int rem = sub & 127; int b = rem >> 4, lc = rem & 15;
        int lane = t & 31, w = t >> 5;
        int mh = t >> 7, lloc = t & 127;      // score-phase mapping
        int lglob = lc*128 + lloc;
        const ulonglong2* qg = reinterpret_cast<const ulonglong2*>(&g_qt[(b*LP+lglob)*CQ]);
        ulonglong2 qa = qg[0], qb = qg[1];
        float d[8][4];
        #pragma unroll
        for(int i=0;i<8;i++){ d[i][0]=0.f; d[i][1]=0.f; d[i][2]=0.f; d[i][3]=0.f; }
        float Sp = 0.f;
        unsigned psb = smem_u32(Psm), vsb = smem_u32(vsmT);
        int mat = lane >> 3, mi8 = lane & 7;
        unsigned aaddr = psb + (unsigned)((w*16 + mi8 + (mat&1)*8)*144 + ((mat>>1)*8)*2);
        unsigned baddr[4];
        #pragma unroll
        for(int p=0;p<4;p++)
            baddr[p] = vsb + (unsigned)((p*16 + (mat>>1)*8 + mi8)*144 + (mat&1)*16);
        for(int mt=0; mt<8; mt++){
            int m0 = z*512 + mt*64;
            __syncthreads();
            if(t < 128){
                int row = t >> 1, h = t & 1;
                *reinterpret_cast<float4*>(&ksm[row*8 + h*4]) =
                    *reinterpret_cast<const float4*>(&g_kt[(b*LP + m0 + row)*CQ + h*4]);
            }
            #pragma unroll
            for(int r=0;r<2;r++){
                int idx = t + 256*r;
                int row = idx >> 3, col8 = idx & 7;
                *reinterpret_cast<uint4*>(&vsmT[row][col8*8]) =
                    *reinterpret_cast<const uint4*>(&g_vtb[(b*IC+row)*LP + m0 + col8*8]);
            }
            __syncthreads();
            {
                unsigned pk[16];
                int mbase = mh*32;
                #pragma unroll
                for(int mi=0; mi<32; mi+=2){
                    const ulonglong2* kp = reinterpret_cast<const ulonglong2*>(&ksm[(mbase+mi)*8]);
                    ulonglong2 k0 = kp[0], k1 = kp[1];
                    ulonglong2 k2 = kp[2], k3 = kp[3];
                    unsigned long long s2 = fmul2(qa.x, k0.x);
                    s2 = ffma2(qa.y, k0.y, s2);
                    s2 = ffma2(qb.x, k1.x, s2);
                    s2 = ffma2(qb.y, k1.y, s2);
                    float2 sp0 = upk2(s2);
                    float e0 = __expf(sp0.x + sp0.y);
                    unsigned long long u2 = fmul2(qa.x, k2.x);
                    u2 = ffma2(qa.y, k2.y, u2);
                    u2 = ffma2(qb.x, k3.x, u2);
                    u2 = ffma2(qb.y, k3.y, u2);
                    float2 sp1 = upk2(u2);
                    float e1 = __expf(sp1.x + sp1.y);
                    Sp += e0 + e1;
                    pk[mi>>1] = cvtbf2(e1, e0);
                }
                uint4* pd = reinterpret_cast<uint4*>(reinterpret_cast<char*>(Psm) + lloc*144 + mh*64);
                const uint4* ps = reinterpret_cast<const uint4*>(pk);
                pd[0] = ps[0]; pd[1] = ps[1]; pd[2] = ps[2]; pd[3] = ps[3];
            }
            __syncthreads();
            #pragma unroll
            for(int ks=0; ks<4; ks++){
                unsigned a0,a1,a2,a3;
                ldmx4(a0,a1,a2,a3, aaddr + ks*32);
                #pragma unroll
                for(int p=0;p<4;p++){
                    unsigned b0,b1,b2,b3;
                    ldmx4(b0,b1,b2,b3, baddr[p] + ks*32);
                    mma16816(d[2*p][0],d[2*p][1],d[2*p][2],d[2*p][3], a0,a1,a2,a3, b0,b1);
                    mma16816(d[2*p+1][0],d[2*p+1][1],d[2*p+1][2],d[2*p+1][3], a0,a1,a2,a3, b2,b3);
                }
            }
        }
        Ssm[t] = Sp;
        __syncthreads();
        if(t < 128)
            g_pamS[(z*NB+b)*LP + lc*128 + t] = Ssm[t] + Ssm[128+t];
        // write accumulators to pamacc [z][b][ch][l]
        int g = lane >> 2, tid4 = lane & 3;
        float* op = g_pamacc + ((z*NB+b)*IC)*LP + lc*128 + w*16;
        #pragma unroll
        for(int nb=0; nb<8; nb++){
            int ch = nb*8 + tid4*2;
            op[ch*LP + g]        = d[nb][0];
            op[(ch+1)*LP + g]    = d[nb][1];
            op[ch*LP + g+8]      = d[nb][2];
            op[(ch+1)*LP + g+8]  = d[nb][3];
        }
    } else {
        int g = sub - 512;
        int rg = t >> 6, dd = t & 63;
        int row = g*4 + rg;
        int b = row >> 6, c = row & 63;
        float E = 0.f;
        #pragma unroll 8
        for(int p=0;p<NSPLIT;p++) E += g_epart[((b*NSPLIT+p)*IC + c)*IC + dd];
        int base = rg*64;
        Ssm[base+dd] = E; __syncthreads();
        for(int off=32;off;off>>=1){ if(dd<off) Ssm[base+dd] = fminf(Ssm[base+dd], Ssm[base+dd+off]); __syncthreads(); }
        float mn = Ssm[base]; __syncthreads();
        float pe = __expf(mn - E);
        Ssm[base+dd] = pe; __syncthreads();
        for(int off=32;off;off>>=1){ if(dd<off) Ssm[base+dd] += Ssm[base+dd+off]; __syncthreads(); }
        float inv = 1.f/Ssm[base];
        g_attnT[(b*IC + dd)*IC + c] = pe*inv;
    }
}

// ---------------- Stage C: PAM merge (0..255) + CAM apply (256..383) ----------------
__global__ __launch_bounds__(256) void k_stageC(const float* __restrict__ gamma_pam,
                                                const float* __restrict__ gamma_cam){
    int t = threadIdx.x;
    int sub = blockIdx.x;
    __shared__ __align__(16) float atsm[64][36];
    if(sub < 256){
        int zq = sub >> 6;
        int rem = sub & 63; int b = rem >> 3, lc = rem & 7;
        int l = lc*256 + t;
        float S = 0.f;
        #pragma unroll
        for(int z=0;z<MSPLIT;z++) S += g_pamS[(z*NB+b)*LP + l];
        float inv = 1.0f/S;
        float gm = gamma_pam[0];
        const float* f1 = &g_feat[b*IC*LP];
        float* outp = &g_safeat[b*IC*LP];
        #pragma unroll 4
        for(int ci=0; ci<16; ci++){
            int ch = zq*16 + ci;
            float s = 0.f;
            #pragma unroll
            for(int z=0;z<MSPLIT;z++) s += g_pamacc[((z*NB+b)*IC+ch)*LP + l];
            outp[ch*LP + l] = gm*(s*inv) + f1[ch*LP + l];
        }
    } else {
        int e = sub - 256;
        int half = e >> 6;
        int rem = e & 63; int b = rem >> 3, lc = rem & 7;
        int l = lc*256 + t;
        for(int idx=t; idx<64*32; idx+=256){
            int d = idx >> 5, c = idx & 31;
            atsm[d][c] = g_attnT[b*4096 + d*64 + half*32 + c];
        }
        __syncthreads();
        unsigned long long acc[16];
        #pragma unroll
        for(int i=0;i<16;i++) acc[i]=0ull;
        const float* f2 = &g_feat[(NB+b)*IC*LP];
        #pragma unroll 8
        for(int d=0; d<64; d++){
            float fv = f2[d*LP + l];
            unsigned long long xx = pk2(fv, fv);
            const ulonglong2* ar = reinterpret_cast<const ulonglong2*>(&atsm[d][0]);
            #pragma unroll
            for(int j=0;j<8;j++){
                ulonglong2 a2 = ar[j];
                acc[2*j]   = ffma2(xx, a2.x, acc[2*j]);
                acc[2*j+1] = ffma2(xx, a2.y, acc[2*j+1]);
            }
        }
        float gm = gamma_cam[0];
        float* outp = &g_scfeat[b*IC*LP];
        #pragma unroll
        for(int j=0;j<16;j++){
            float2 p = upk2(acc[j]);
            int c = half*32 + 2*j;
            outp[c*LP+l]     = gm*p.x + f2[c*LP+l];
            outp[(c+1)*LP+l] = gm*p.y + f2[(c+1)*LP+l];
        }
    }
}

// ---------------- conv3: full 64 outs per block; z=(br,ih) ----------------
__global__ __launch_bounds__(256) void k_conv3(const float* __restrict__ W51, const float* __restrict__ W52){
    int t=threadIdx.x; int l0 = blockIdx.x*256; int l = l0+t; int b=blockIdx.y;
    int z=blockIdx.z; int br = z >> 1, ih = z & 1;
    const float* W  = br ? W52 : W51;
    const float* in = br ? &g_scfeat[b*IC*LP] : &g_safeat[b*IC*LP];
    __shared__ __align__(16) float insm[32][258];
    __shared__ __align__(16) float wsm[96][68];
    unsigned long long acc[32];
    #pragma unroll
    for(int i=0;i<32;i++) acc[i]=0ull;
    for(int idx=t; idx<32*258; idx+=256){
        int ic = idx/258, pos = idx - ic*258;
        int ll = l0 + pos - 1;
        insm[ic][pos] = (ll>=0 && ll<LP) ? in[(ih*32+ic)*LP + ll] : 0.f;
    }
    for(int idx=t; idx<32*3*64; idx+=256){
        int o = idx & 63; int rest = idx >> 6; int ic = rest/3, j = rest - ic*3;
        wsm[ic*3+j][o] = W[(o*IC + ih*32+ic)*3 + j];
    }
    __syncthreads();
    for(int ic=0; ic<32; ic++){
        float xv[3] = { insm[ic][t], insm[ic][t+1], insm[ic][t+2] };
        #pragma unroll
        for(int j=0;j<3;j++){
            unsigned long long xx = pk2(xv[j], xv[j]);
            const ulonglong2* wr = reinterpret_cast<const ulonglong2*>(&wsm[ic*3+j][0]);
            #pragma unroll
            for(int q=0;q<16;q++){
                ulonglong2 w2 = wr[q];
                acc[2*q]   = ffma2(xx, w2.x, acc[2*q]);
                acc[2*q+1] = ffma2(xx, w2.y, acc[2*q+1]);
            }
        }
    }
    float* out = (ih ? g_y2 : g_y) + (br*NB+b)*IC*LP;
    #pragma unroll
    for(int q=0;q<32;q++){
        float2 p = upk2(acc[q]);
        out[(2*q)*LP + l]   = p.x;
        out[(2*q+1)*LP + l] = p.y;
    }
}

// ---------------- outconv (0..255) + sasc (256) ----------------
__global__ __launch_bounds__(256) void k_outconv(const float* __restrict__ W6, const float* __restrict__ b6,
        const float* __restrict__ W7, const float* __restrict__ b7,
        const float* __restrict__ W8, const float* __restrict__ b8,
        float* __restrict__ dout){
    int t=threadIdx.x;
    int sub = blockIdx.x;
    if(sub == 256){
        __shared__ float cm[NB*IC];
        if(t < 256) { cm[t] = g_cm[t]*(1.0f/LP); cm[t+256] = g_cm[t+256]*(1.0f/LP); }
        __syncthreads();
        #pragma unroll
        for(int r=0;r<4;r++){
            int o = r*256 + t;
            int b = o >> 7, oc = o & 127;
            float s = b8[oc];
            #pragma unroll 8
            for(int ic=0; ic<64; ic++) s += W8[oc*64+ic]*cm[b*64+ic];
            dout[b*128+oc] = s;
        }
        return;
    }
    int z = sub >> 6;
    int rem = sub & 63; int b = rem >> 3, lc = rem & 7;
    int l0 = lc*256; int l = l0+t;
    int br = z >> 1, oh = z & 1;
    const float* W    = br ? W7 : W6;
    const float* bias = br ? b7 : b6;
    const float* in = &g_conv[(br*NB+b)*IC*LP];
    float* out = dout + 1024 + br*(NB*OCH*LP) + (b*OCH + oh*64)*LP;
    __shared__ __align__(16) float insm[32][256];
    __shared__ __align__(16) float wsm[32][68];
    unsigned long long acc[32];
    #pragma unroll
    for(int i=0;i<32;i++) acc[i]=0ull;
    for(int cc=0;cc<2;cc++){
        __syncthreads();
        for(int idx=t; idx<32*256; idx+=256){
            int ic = idx >> 8, ll = idx & 255;
            insm[ic][ll] = in[(cc*32+ic)*LP + l0 + ll];
        }
        for(int idx=t; idx<32*64; idx+=256){
            int ic = idx & 31, o = idx >> 5;
            wsm[ic][o] = W[(oh*64+o)*IC + cc*32 + ic];
        }
        __syncthreads();
        for(int ic=0; ic<32; ic++){
            float fv = insm[ic][t];
            unsigned long long xx = pk2(fv,fv);
            const ulonglong2* wr = reinterpret_cast<const ulonglong2*>(&wsm[ic][0]);
            #pragma unroll
            for(int q=0;q<16;q++){
                ulonglong2 w2 = wr[q];
                acc[2*q]   = ffma2(xx, w2.x, acc[2*q]);
                acc[2*q+1] = ffma2(xx, w2.y, acc[2*q+1]);
            }
        }
    }
    #pragma unroll
    for(int q=0;q<32;q++){
        float2 p = upk2(acc[q]);
        int o = 2*q;
        out[o*LP + l]     = p.x + bias[oh*64+o];
        out[(o+1)*LP + l] = p.y + bias[oh*64+o+1];
    }
}

// ---------------- launch ----------------
extern "C" void kernel_launch(void* const* d_in, const int* in_sizes, int n_in,
                              void* d_out, int out_size){
    (void)in_sizes; (void)n_in; (void)out_size;
    const float* x   = (const float*)d_in[0];
    const float* W5a = (const float*)d_in[1];
    const float* g5a = (const float*)d_in[2];
    const float* b5a = (const float*)d_in[3];
    const float* W5c = (const float*)d_in[4];
    const float* g5c = (const float*)d_in[5];
    const float* b5c = (const float*)d_in[6];
    const float* Wq  = (const float*)d_in[7];
    const float* bq  = (const float*)d_in[8];
    const float* Wk  = (const float*)d_in[9];
    const float* bk  = (const float*)d_in[10];
    const float* Wv  = (const float*)d_in[11];
    const float* bv  = (const float*)d_in[12];
    const float* gpam= (const float*)d_in[13];
    const float* gcam= (const float*)d_in[14];
    const float* W51 = (const float*)d_in[15];
    const float* g51 = (const float*)d_in[16];
    const float* b51 = (const float*)d_in[17];
    const float* W52 = (const float*)d_in[18];
    const float* g52 = (const float*)d_in[19];
    const float* b52 = (const float*)d_in[20];
    const float* W6  = (const float*)d_in[21];
    const float* b6  = (const float*)d_in[22];
    const float* W7  = (const float*)d_in[23];
    const float* b7  = (const float*)d_in[24];
    const float* W8  = (const float*)d_in[25];
    const float* b8  = (const float*)d_in[26];
    float* out = (float*)d_out;

    k_conv1<<<dim3(8,8,4),256>>>(x, W5a, W5c);
    k_bnstats<<<dim3(128,4),256>>>(0);
    k_bnapply<<<2048,256>>>(0, g5a,b5a,g5c,b5c);

    k_stageA<<<448,256>>>(Wq,bq,Wk,bk,Wv,bv);
    k_stageB<<<640,256>>>();
    k_stageC<<<384,256>>>(gpam,gcam);

    k_conv3<<<dim3(8,8,4),256>>>(W51,W52);
    k_bnstats<<<dim3(128,4),256>>>(1);
    k_bnapply<<<2048,256>>>(1, g51,b51,g52,b52);

    k_outconv<<<257,256>>>(W6,b6,W7,b7,W8,b8,out);
}

// round 14
// speedup vs baseline: 1.1324x; 1.1026x over previous
#include <cuda_runtime.h>
#include <cuda_bf16.h>

#define NB 8
#define NC 256
#define LIN 2046
#define LP 2048
#define IC 64
#define CQ 8
#define OCH 128
#define NSPLIT 32
#define MSPLIT 4

// ---------------- scratch ----------------
__device__ float g_y [2*NB*IC*LP];       // conv partial (in-half 0) / conv3 full
__device__ float g_y2[2*NB*IC*LP];       // conv partial (in-half 1)
__device__ float g_feat[2*NB*IC*LP];
__device__ float g_bnps[2][512];
__device__ float g_bnpq[2][512];
__device__ float g_qt[NB*LP*CQ];
__device__ float g_kt[NB*LP*CQ];
__device__ __nv_bfloat16 g_vtb[NB*IC*LP];   // V transposed [b][c][m], bf16
__device__ float g_pamacc[MSPLIT*NB*IC*LP]; // partial acc [z][b][ch][l], fp32
__device__ float g_pamS[MSPLIT*NB*LP];
__device__ float g_safeat[NB*IC*LP];
__device__ float g_scfeat[NB*IC*LP];
__device__ float g_epart[NB*NSPLIT*IC*IC];
__device__ float g_attnT[NB*IC*IC];
__device__ float g_conv[2*NB*IC*LP];
__device__ float g_cm[NB*IC];

// ---------------- helpers ----------------
__device__ __forceinline__ unsigned long long pk2(float a, float b){
    unsigned long long r; asm("mov.b64 %0, {%1, %2};" : "=l"(r) : "f"(a), "f"(b)); return r;
}
__device__ __forceinline__ float2 upk2(unsigned long long a){
    float2 r; asm("mov.b64 {%0, %1}, %2;" : "=f"(r.x), "=f"(r.y) : "l"(a)); return r;
}
__device__ __forceinline__ unsigned long long ffma2(unsigned long long a, unsigned long long b, unsigned long long c){
    unsigned long long d; asm("fma.rn.f32x2 %0, %1, %2, %3;" : "=l"(d) : "l"(a), "l"(b), "l"(c)); return d;
}
__device__ __forceinline__ unsigned long long fmul2(unsigned long long a, unsigned long long b){
    unsigned long long d; asm("mul.rn.f32x2 %0, %1, %2;" : "=l"(d) : "l"(a), "l"(b)); return d;
}
__device__ __forceinline__ unsigned smem_u32(const void* p){
    unsigned r; asm("{ .reg .u64 t; cvta.to.shared.u64 t, %1; cvt.u32.u64 %0, t; }" : "=r"(r) : "l"(p)); return r;
}
__device__ __forceinline__ void ldmx4(unsigned &r0, unsigned &r1, unsigned &r2, unsigned &r3, unsigned addr){
    asm volatile("ldmatrix.sync.aligned.m8n8.x4.shared.b16 {%0,%1,%2,%3}, [%4];"
        : "=r"(r0),"=r"(r1),"=r"(r2),"=r"(r3) : "r"(addr));
}
__device__ __forceinline__ void mma16816(float &d0,float &d1,float &d2,float &d3,
        unsigned a0,unsigned a1,unsigned a2,unsigned a3,unsigned b0,unsigned b1){
    asm volatile("mma.sync.aligned.m16n8k16.row.col.f32.bf16.bf16.f32 "
        "{%0,%1,%2,%3}, {%4,%5,%6,%7}, {%8,%9}, {%0,%1,%2,%3};"
        : "+f"(d0),"+f"(d1),"+f"(d2),"+f"(d3)
        : "r"(a0),"r"(a1),"r"(a2),"r"(a3),"r"(b0),"r"(b1));
}
__device__ __forceinline__ void mmatf32(float &d0,float &d1,float &d2,float &d3,
        unsigned a0,unsigned a1,unsigned a2,unsigned a3,unsigned b0,unsigned b1){
    asm volatile("mma.sync.aligned.m16n8k8.row.col.f32.tf32.tf32.f32 "
        "{%0,%1,%2,%3}, {%4,%5,%6,%7}, {%8,%9}, {%0,%1,%2,%3};"
        : "+f"(d0),"+f"(d1),"+f"(d2),"+f"(d3)
        : "r"(a0),"r"(a1),"r"(a2),"r"(a3),"r"(b0),"r"(b1));
}
__device__ __forceinline__ unsigned cvtbf2(float hi, float lo){
    unsigned r; asm("cvt.rn.bf16x2.f32 %0, %1, %2;" : "=r"(r) : "f"(hi), "f"(lo)); return r;
}
__device__ __forceinline__ unsigned tf32r(float v){
    unsigned r; asm("cvt.rna.tf32.f32 %0, %1;" : "=r"(r) : "f"(v)); return r;
}

// ---------------- conv1x1: both branches fused; z=(ih,oh); also zeroes g_cm ----------------
__global__ __launch_bounds__(256) void k_conv1(const float* __restrict__ x,
        const float* __restrict__ W5a, const float* __restrict__ W5c){
    int t = threadIdx.x;
    int lt = blockIdx.x*256 + t;
    int b = blockIdx.y;
    int z = blockIdx.z; int ih = z >> 1, oh = z & 1;
    if(blockIdx.x == 0 && z == 0 && t < 64) g_cm[b*64 + t] = 0.f;
    __shared__ __align__(16) float wsa[64][36];
    __shared__ __align__(16) float wsc[64][36];
    unsigned long long accA[16], accC[16];
    #pragma unroll
    for(int i=0;i<16;i++){ accA[i]=0ull; accC[i]=0ull; }
    bool valid = (lt>=1 && lt<=LIN);
    int lsrc = lt-1;
    for(int ci=0; ci<2; ci++){
        int cc = ih*2 + ci;
        __syncthreads();
        for(int idx=t; idx<64*32; idx+=256){
            int c = idx & 63, o = idx >> 6;
            wsa[c][o] = W5a[(oh*32+o)*256 + cc*64 + c];
            wsc[c][o] = W5c[(oh*32+o)*256 + cc*64 + c];
        }
        __syncthreads();
        if(valid){
            #pragma unroll 4
            for(int c=0;c<64;c++){
                float xv = x[(b*NC + cc*64 + c)*LIN + lsrc];
                unsigned long long xx = pk2(xv,xv);
                #pragma unroll
                for(int j=0;j<8;j++){
                    ulonglong2 wa = *reinterpret_cast<const ulonglong2*>(&wsa[c][4*j]);
                    accA[2*j]   = ffma2(xx, wa.x, accA[2*j]);
                    accA[2*j+1] = ffma2(xx, wa.y, accA[2*j+1]);
                }
                #pragma unroll
                for(int j=0;j<8;j++){
                    ulonglong2 wc = *reinterpret_cast<const ulonglong2*>(&wsc[c][4*j]);
                    accC[2*j]   = ffma2(xx, wc.x, accC[2*j]);
                    accC[2*j+1] = ffma2(xx, wc.y, accC[2*j+1]);
                }
            }
        }
    }
    float* base = (ih ? g_y2 : g_y);
    float* outA = base + (0*NB + b)*IC*LP;
    float* outC = base + (1*NB + b)*IC*LP;
    #pragma unroll
    for(int j=0;j<16;j++){
        float2 pa = upk2(accA[j]);
        outA[(oh*32+2*j)*LP   + lt] = pa.x;
        outA[(oh*32+2*j+1)*LP + lt] = pa.y;
    }
    #pragma unroll
    for(int j=0;j<16;j++){
        float2 pc = upk2(accC[j]);
        outC[(oh*32+2*j)*LP   + lt] = pc.x;
        outC[(oh*32+2*j+1)*LP + lt] = pc.y;
    }
}

// ---------------- BN stats partials ----------------
__global__ __launch_bounds__(256) void k_bnstats(int sel, int dual){
    int ch = blockIdx.x & 63, br = blockIdx.x >> 6;
    int sl = blockIdx.y;
    int t = threadIdx.x;
    float s=0.f, sq=0.f;
    for(int bb=0;bb<2;bb++){
        int b = sl*2+bb;
        const float4* p  = reinterpret_cast<const float4*>(&g_y [((br*NB+b)*IC + ch)*LP]);
        const float4* p2 = reinterpret_cast<const float4*>(&g_y2[((br*NB+b)*IC + ch)*LP]);
        if(dual){
            for(int i=t;i<LP/4;i+=256){
                float4 v = p[i], w = p2[i];
                v.x+=w.x; v.y+=w.y; v.z+=w.z; v.w+=w.w;
                s  += v.x+v.y+v.z+v.w;
                sq += v.x*v.x + v.y*v.y + v.z*v.z + v.w*v.w;
            }
        } else {
            for(int i=t;i<LP/4;i+=256){
                float4 v = p[i];
                s  += v.x+v.y+v.z+v.w;
                sq += v.x*v.x + v.y*v.y + v.z*v.z + v.w*v.w;
            }
        }
    }
    __shared__ float rs[256], rq[256];
    rs[t]=s; rq[t]=sq; __syncthreads();
    for(int off=128;off;off>>=1){
        if(t<off){ rs[t]+=rs[t+off]; rq[t]+=rq[t+off]; }
        __syncthreads();
    }
    if(t==0){
        g_bnps[sel][(br*64+ch)*4+sl] = rs[0];
        g_bnpq[sel][(br*64+ch)*4+sl] = rq[0];
    }
}

// ---------------- BN apply + ReLU (+fused colmean when sel=1) ----------------
__global__ __launch_bounds__(256) void k_bnapply(int sel, int dual,
                          const float* __restrict__ g0, const float* __restrict__ be0,
                          const float* __restrict__ g1, const float* __restrict__ be1){
    float* out = sel ? g_conv : g_feat;
    int i4 = blockIdx.x*blockDim.x + threadIdx.x;
    int t = threadIdx.x;
    int flat = i4*4;
    int ch = (flat >> 11) & 63;
    int b  = (flat >> 17) & 7;
    int br = flat >> 20;
    float s=0.f, sq=0.f;
    #pragma unroll
    for(int sl=0;sl<4;sl++){
        s  += g_bnps[sel][(br*64+ch)*4+sl];
        sq += g_bnpq[sel][(br*64+ch)*4+sl];
    }
    const float inv = 1.0f/(NB*LP);
    float mean = s*inv;
    float var  = sq*inv - mean*mean;
    float rstd = rsqrtf(var + 1e-5f);
    float gm = br ? g1[ch] : g0[ch];
    float be = br ? be1[ch] : be0[ch];
    float sc = rstd*gm, sh = be - mean*sc;
    float4 v = reinterpret_cast<const float4*>(g_y)[i4];
    if(dual){
        float4 w = reinterpret_cast<const float4*>(g_y2)[i4];
        v.x+=w.x; v.y+=w.y; v.z+=w.z; v.w+=w.w;
    }
    v.x = fmaxf(v.x*sc+sh, 0.f);
    v.y = fmaxf(v.y*sc+sh, 0.f);
    v.z = fmaxf(v.z*sc+sh, 0.f);
    v.w = fmaxf(v.w*sc+sh, 0.f);
    reinterpret_cast<float4*>(out)[i4] = v;
    if(sel){
        __shared__ float rsum[256];
        rsum[t] = v.x+v.y+v.z+v.w;
        __syncthreads();
        for(int off=128;off;off>>=1){
            if(t<off) rsum[t]+=rsum[t+off];
            __syncthreads();
        }
        if(t==0) atomicAdd(&g_cm[b*IC+ch], rsum[0]);
    }
}

// ---------------- Stage A: qkv 3-way (0..191) + CAM energy (192..447) ----------------
__global__ __launch_bounds__(256) void k_stageA(const float* __restrict__ Wq, const float* __restrict__ bq,
        const float* __restrict__ Wk, const float* __restrict__ bk,
        const float* __restrict__ Wv, const float* __restrict__ bv){
    int t = threadIdx.x;
    int sub = blockIdx.x;
    __shared__ __align__(16) float ws[64][36];
    __shared__ float fsm[64][65];
    if(sub < 192){
        int zz = sub / 64;
        int rem = sub - zz*64; int b = rem >> 3, lc = rem & 7;
        int l = lc*256 + t;
        const float* f1 = &g_feat[b*IC*LP];
        if(zz == 0){
            for(int idx=t; idx<64*16; idx+=256){
                int c = idx & 63, o = idx >> 6;
                ws[c][o] = (o<8) ? Wq[o*64+c] : Wk[(o-8)*64+c];
            }
            __syncthreads();
            unsigned long long acc[8];
            #pragma unroll
            for(int i=0;i<8;i++) acc[i]=0ull;
            #pragma unroll 8
            for(int c=0;c<64;c++){
                float fv = f1[c*LP + l];
                unsigned long long xx = pk2(fv,fv);
                #pragma unroll
                for(int j=0;j<4;j++){
                    ulonglong2 w2 = *reinterpret_cast<const ulonglong2*>(&ws[c][4*j]);
                    acc[2*j]   = ffma2(xx, w2.x, acc[2*j]);
                    acc[2*j+1] = ffma2(xx, w2.y, acc[2*j+1]);
                }
            }
            float* qp = &g_qt[(b*LP+l)*CQ];
            float* kp = &g_kt[(b*LP+l)*CQ];
            #pragma unroll
            for(int j=0;j<4;j++){
                float2 p = upk2(acc[j]);
                qp[2*j]   = p.x + bq[2*j];
                qp[2*j+1] = p.y + bq[2*j+1];
            }
            #pragma unroll
            for(int j=4;j<8;j++){
                float2 p = upk2(acc[j]);
                kp[2*(j-4)]   = p.x + bk[2*(j-4)];
                kp[2*(j-4)+1] = p.y + bk[2*(j-4)+1];
            }
        } else {
            int half = zz-1;
            for(int idx=t; idx<64*32; idx+=256){
                int c = idx & 63, o = idx >> 6;
                ws[c][o] = Wv[(half*32+o)*64 + c];
            }
            __syncthreads();
            unsigned long long acc[16];
            #pragma unroll
            for(int i=0;i<16;i++) acc[i]=0ull;
            #pragma unroll 8
            for(int c=0;c<64;c++){
                float fv = f1[c*LP + l];
                unsigned long long xx = pk2(fv,fv);
                #pragma unroll
                for(int j=0;j<8;j++){
                    ulonglong2 w2 = *reinterpret_cast<const ulonglong2*>(&ws[c][4*j]);
                    acc[2*j]   = ffma2(xx, w2.x, acc[2*j]);
                    acc[2*j+1] = ffma2(xx, w2.y, acc[2*j+1]);
                }
            }
            #pragma unroll
            for(int j=0;j<16;j++){
                float2 p = upk2(acc[j]);
                int c = half*32 + 2*j;
                g_vtb[(b*IC + c)*LP + l]   = __float2bfloat16(p.x + bv[c]);
                g_vtb[(b*IC + c+1)*LP + l] = __float2bfloat16(p.y + bv[c+1]);
            }
        }
    } else {
        // CAM energy
        int e = sub - 192; int b = e >> 5, ls = e & 31;
        int d = t & 63, cw = t >> 6;
        float acc[16];
        #pragma unroll
        for(int i=0;i<16;i++) acc[i]=0.f;
        const float* f2 = &g_feat[(NB + b)*IC*LP];
        int l0 = ls*(LP/NSPLIT);
        for(int idx=t; idx<64*64; idx+=256){
            int c = idx >> 6, ll = idx & 63;
            fsm[c][ll] = f2[c*LP + l0 + ll];
        }
        __syncthreads();
        for(int ll=0; ll<64; ll++){
            float fd = fsm[d][ll];
            #pragma unroll
            for(int i=0;i<16;i++) acc[i] += fsm[cw*16+i][ll]*fd;
        }
        float* ep = &g_epart[((b*NSPLIT+ls)*IC)*IC];
        #pragma unroll
        for(int i=0;i<16;i++) ep[(cw*16+i)*IC + d] = acc[i];
    }
}

// ---------------- Stage B: PAM tensor-core (0..511) + CAM softmax (512..639) ----------------
__global__ __launch_bounds__(256) void k_stageB(){
    int t = threadIdx.x;
    int sub = blockIdx.x;
    __shared__ __align__(16) float ksm[64*8];
    __shared__ __align__(16) __nv_bfloat16 vsmT[64][72];
    __shared__ __align__(16) __nv_bfloat16 Psm[128][72];
    __shared__ float Ssm[256];
    if(sub < 512){
        int z = sub >> 7;
        int rem = sub & 127; int b = rem >> 4, lc = rem & 15;
        int lane = t & 31, w = t >> 5;
        int mh = t >> 7, lloc = t & 127;
        int lglob = lc*128 + lloc;
        const ulonglong2* qg = reinterpret_cast<const ulonglong2*>(&g_qt[(b*LP+lglob)*CQ]);
        ulonglong2 qa = qg[0], qb = qg[1];
        float d[8][4];
        #pragma unroll
        for(int i=0;i<8;i++){ d[i][0]=0.f; d[i][1]=0.f; d[i][2]=0.f; d[i][3]=0.f; }
        float Sp = 0.f;
        unsigned psb = smem_u32(Psm), vsb = smem_u32(vsmT);
        int mat = lane >> 3, mi8 = lane & 7;
        unsigned aaddr = psb + (unsigned)((w*16 + mi8 + (mat&1)*8)*144 + ((mat>>1)*8)*2);
        unsigned baddr[4];
        #pragma unroll
        for(int p=0;p<4;p++)
            baddr[p] = vsb + (unsigned)((p*16 + (mat>>1)*8 + mi8)*144 + (mat&1)*16);
        for(int mt=0; mt<8; mt++){
            int m0 = z*512 + mt*64;
            __syncthreads();
            if(t < 128){
                int row = t >> 1, h = t & 1;
                *reinterpret_cast<float4*>(&ksm[row*8 + h*4]) =
                    *reinterpret_cast<const float4*>(&g_kt[(b*LP + m0 + row)*CQ + h*4]);
            }
            #pragma unroll
            for(int r=0;r<2;r++){
                int idx = t + 256*r;
                int row = idx >> 3, col8 = idx & 7;
                *reinterpret_cast<uint4*>(&vsmT[row][col8*8]) =
                    *reinterpret_cast<const uint4*>(&g_vtb[(b*IC+row)*LP + m0 + col8*8]);
            }
            __syncthreads();
            {
                unsigned pk[16];
                int mbase = mh*32;
                #pragma unroll
                for(int mi=0; mi<32; mi+=2){
                    const ulonglong2* kp = reinterpret_cast<const ulonglong2*>(&ksm[(mbase+mi)*8]);
                    ulonglong2 k0 = kp[0], k1 = kp[1];
                    ulonglong2 k2 = kp[2], k3 = kp[3];
                    unsigned long long s2 = fmul2(qa.x, k0.x);
                    s2 = ffma2(qa.y, k0.y, s2);
                    s2 = ffma2(qb.x, k1.x, s2);
                    s2 = ffma2(qb.y, k1.y, s2);
                    float2 sp0 = upk2(s2);
                    float e0 = __expf(sp0.x + sp0.y);
                    unsigned long long u2 = fmul2(qa.x, k2.x);
                    u2 = ffma2(qa.y, k2.y, u2);
                    u2 = ffma2(qb.x, k3.x, u2);
                    u2 = ffma2(qb.y, k3.y, u2);
                    float2 sp1 = upk2(u2);
                    float e1 = __expf(sp1.x + sp1.y);
                    Sp += e0 + e1;
                    pk[mi>>1] = cvtbf2(e1, e0);
                }
                uint4* pd = reinterpret_cast<uint4*>(reinterpret_cast<char*>(Psm) + lloc*144 + mh*64);
                const uint4* ps = reinterpret_cast<const uint4*>(pk);
                pd[0] = ps[0]; pd[1] = ps[1]; pd[2] = ps[2]; pd[3] = ps[3];
            }
            __syncthreads();
            #pragma unroll
            for(int ks=0; ks<4; ks++){
                unsigned a0,a1,a2,a3;
                ldmx4(a0,a1,a2,a3, aaddr + ks*32);
                #pragma unroll
                for(int p=0;p<4;p++){
                    unsigned b0,b1,b2,b3;
                    ldmx4(b0,b1,b2,b3, baddr[p] + ks*32);
                    mma16816(d[2*p][0],d[2*p][1],d[2*p][2],d[2*p][3], a0,a1,a2,a3, b0,b1);
                    mma16816(d[2*p+1][0],d[2*p+1][1],d[2*p+1][2],d[2*p+1][3], a0,a1,a2,a3, b2,b3);
                }
            }
        }
        Ssm[t] = Sp;
        __syncthreads();
        if(t < 128)
            g_pamS[(z*NB+b)*LP + lc*128 + t] = Ssm[t] + Ssm[128+t];
        int g = lane >> 2, tid4 = lane & 3;
        float* op = g_pamacc + ((z*NB+b)*IC)*LP + lc*128 + w*16;
        #pragma unroll
        for(int nb=0; nb<8; nb++){
            int ch = nb*8 + tid4*2;
            op[ch*LP + g]        = d[nb][0];
            op[(ch+1)*LP + g]    = d[nb][1];
            op[ch*LP + g+8]      = d[nb][2];
            op[(ch+1)*LP + g+8]  = d[nb][3];
        }
    } else {
        int g = sub - 512;
        int rg = t >> 6, dd = t & 63;
        int row = g*4 + rg;
        int b = row >> 6, c = row & 63;
        float E = 0.f;
        #pragma unroll 8
        for(int p=0;p<NSPLIT;p++) E += g_epart[((b*NSPLIT+p)*IC + c)*IC + dd];
        int base = rg*64;
        Ssm[base+dd] = E; __syncthreads();
        for(int off=32;off;off>>=1){ if(dd<off) Ssm[base+dd] = fminf(Ssm[base+dd], Ssm[base+dd+off]); __syncthreads(); }
        float mn = Ssm[base]; __syncthreads();
        float pe = __expf(mn - E);
        Ssm[base+dd] = pe; __syncthreads();
        for(int off=32;off;off>>=1){ if(dd<off) Ssm[base+dd] += Ssm[base+dd+off]; __syncthreads(); }
        float inv = 1.f/Ssm[base];
        g_attnT[(b*IC + dd)*IC + c] = pe*inv;
    }
}

// ---------------- Stage C: PAM merge (0..255) + CAM apply (256..383) ----------------
__global__ __launch_bounds__(256) void k_stageC(const float* __restrict__ gamma_pam,
                                                const float* __restrict__ gamma_cam){
    int t = threadIdx.x;
    int sub = blockIdx.x;
    __shared__ __align__(16) float atsm[64][36];
    if(sub < 256){
        int zq = sub >> 6;
        int rem = sub & 63; int b = rem >> 3, lc = rem & 7;
        int l = lc*256 + t;
        float S = 0.f;
        #pragma unroll
        for(int z=0;z<MSPLIT;z++) S += g_pamS[(z*NB+b)*LP + l];
        float inv = 1.0f/S;
        float gm = gamma_pam[0];
        const float* f1 = &g_feat[b*IC*LP];
        float* outp = &g_safeat[b*IC*LP];
        #pragma unroll 4
        for(int ci=0; ci<16; ci++){
            int ch = zq*16 + ci;
            float s = 0.f;
            #pragma unroll
            for(int z=0;z<MSPLIT;z++) s += g_pamacc[((z*NB+b)*IC+ch)*LP + l];
            outp[ch*LP + l] = gm*(s*inv) + f1[ch*LP + l];
        }
    } else {
        int e = sub - 256;
        int half = e >> 6;
        int rem = e & 63; int b = rem >> 3, lc = rem & 7;
        int l = lc*256 + t;
        for(int idx=t; idx<64*32; idx+=256){
            int d = idx >> 5, c = idx & 31;
            atsm[d][c] = g_attnT[b*4096 + d*64 + half*32 + c];
        }
        __syncthreads();
        unsigned long long acc[16];
        #pragma unroll
        for(int i=0;i<16;i++) acc[i]=0ull;
        const float* f2 = &g_feat[(NB+b)*IC*LP];
        #pragma unroll 8
        for(int d=0; d<64; d++){
            float fv = f2[d*LP + l];
            unsigned long long xx = pk2(fv, fv);
            const ulonglong2* ar = reinterpret_cast<const ulonglong2*>(&atsm[d][0]);
            #pragma unroll
            for(int j=0;j<8;j++){
                ulonglong2 a2 = ar[j];
                acc[2*j]   = ffma2(xx, a2.x, acc[2*j]);
                acc[2*j+1] = ffma2(xx, a2.y, acc[2*j+1]);
            }
        }
        float gm = gamma_cam[0];
        float* outp = &g_scfeat[b*IC*LP];
        #pragma unroll
        for(int j=0;j<16;j++){
            float2 p = upk2(acc[j]);
            int c = half*32 + 2*j;
            outp[c*LP+l]     = gm*p.x + f2[c*LP+l];
            outp[(c+1)*LP+l] = gm*p.y + f2[(c+1)*LP+l];
        }
    }
}

// ---------------- conv3: tf32 tensor-core (3 shifted K=64 GEMMs), dynamic smem ----------------
#define C3_ISTRIDE 76
#define C3_INSZ (130*C3_ISTRIDE)
__global__ __launch_bounds__(256) void k_conv3(const float* __restrict__ W51, const float* __restrict__ W52){
    extern __shared__ float dsm[];
    float* insm = dsm;                      // [130][76] tf32 (as fp32)
    float* wsm  = dsm + C3_INSZ;            // [3][64][76]
    int t = threadIdx.x;
    int lane = t & 31, w = t >> 5;
    int l0 = blockIdx.x*128;
    int b = blockIdx.y, br = blockIdx.z;
    const float* W  = br ? W52 : W51;
    const float* in = br ? &g_scfeat[b*IC*LP] : &g_safeat[b*IC*LP];
    for(int idx=t; idx<64*130; idx+=256){
        int ic = idx/130, r = idx - ic*130;
        int lg = l0 + r - 1;
        float v = (lg>=0 && lg<LP) ? in[ic*LP + lg] : 0.f;
        unsigned u = tf32r(v);
        reinterpret_cast<unsigned*>(insm)[r*C3_ISTRIDE + ic] = u;
    }
    for(int idx=t; idx<64*64*3; idx+=256){
        int o = idx/192; int rest = idx - o*192; int ic = rest/3, j = rest - ic*3;
        unsigned u = tf32r(W[idx]);
        reinterpret_cast<unsigned*>(wsm)[(j*64+o)*C3_ISTRIDE + ic] = u;
    }
    __syncthreads();
    float d[8][4];
    #pragma unroll
    for(int i=0;i<8;i++){ d[i][0]=0.f; d[i][1]=0.f; d[i][2]=0.f; d[i][3]=0.f; }
    unsigned isb = smem_u32(insm), wsb = smem_u32(wsm);
    int mat = lane >> 3, mi8 = lane & 7;
    const unsigned RS = C3_ISTRIDE*4;       // 304 B row stride
    unsigned abase = isb + (unsigned)(w*16 + mi8 + (mat&1)*8)*RS + (unsigned)(mat>>1)*16u;
    unsigned bb[4];
    #pragma unroll
    for(int p=0;p<4;p++)
        bb[p] = wsb + (unsigned)(p*16 + (mat&1)*8 + mi8)*RS + (unsigned)(mat>>1)*16u;
    const unsigned JW = 64u*RS;             // weight j-plane stride
    #pragma unroll
    for(int j=0;j<3;j++){
        #pragma unroll
        for(int ks=0; ks<8; ks++){
            unsigned a0,a1,a2,a3;
            ldmx4(a0,a1,a2,a3, abase + (unsigned)j*RS + ks*32u);
            #pragma unroll
            for(int p=0;p<4;p++){
                unsigned r0,r1,r2,r3;
                ldmx4(r0,r1,r2,r3, bb[p] + (unsigned)j*JW + ks*32u);
                mmatf32(d[2*p][0],d[2*p][1],d[2*p][2],d[2*p][3], a0,a1,a2,a3, r0,r2);
                mmatf32(d[2*p+1][0],d[2*p+1][1],d[2*p+1][2],d[2*p+1][3], a0,a1,a2,a3, r1,r3);
            }
        }
    }
    int g = lane >> 2, tid4 = lane & 3;
    float* out = &g_y[(br*NB+b)*IC*LP] + l0 + w*16;
    #pragma unroll
    for(int nb=0; nb<8; nb++){
        int ch = nb*8 + tid4*2;
        out[ch*LP + g]        = d[nb][0];
        out[(ch+1)*LP + g]    = d[nb][1];
        out[ch*LP + g+8]      = d[nb][2];
        out[(ch+1)*LP + g+8]  = d[nb][3];
    }
}

// ---------------- outconv (0..255) + sasc (256) ----------------
__global__ __launch_bounds__(256) void k_outconv(const float* __restrict__ W6, const float* __restrict__ b6,
        const float* __restrict__ W7, const float* __restrict__ b7,
        const float* __restrict__ W8, const float* __restrict__ b8,
        float* __restrict__ dout){
    int t=threadIdx.x;
    int sub = blockIdx.x;
    if(sub == 256){
        __shared__ float cm[NB*IC];
        if(t < 256) { cm[t] = g_cm[t]*(1.0f/LP); cm[t+256] = g_cm[t+256]*(1.0f/LP); }
        __syncthreads();
        #pragma unroll
        for(int r=0;r<4;r++){
            int o = r*256 + t;
            int b = o >> 7, oc = o & 127;
            float s = b8[oc];
            #pragma unroll 8
            for(int ic=0; ic<64; ic++) s += W8[oc*64+ic]*cm[b*64+ic];
            dout[b*128+oc] = s;
        }
        return;
    }
    int z = sub >> 6;
    int rem = sub & 63; int b = rem >> 3, lc = rem & 7;
    int l0 = lc*256; int l = l0+t;
    int br = z >> 1, oh = z & 1;
    const float* W    = br ? W7 : W6;
    const float* bias = br ? b7 : b6;
    const float* in = &g_conv[(br*NB+b)*IC*LP];
    float* out = dout + 1024 + br*(NB*OCH*LP) + (b*OCH + oh*64)*LP;
    __shared__ __align__(16) float insm[32][256];
    __shared__ __align__(16) float wsm[32][68];
    unsigned long long acc[32];
    #pragma unroll
    for(int i=0;i<32;i++) acc[i]=0ull;
    for(int cc=0;cc<2;cc++){
        __syncthreads();
        for(int idx=t; idx<32*256; idx+=256){
            int ic = idx >> 8, ll = idx & 255;
            insm[ic][ll] = in[(cc*32+ic)*LP + l0 + ll];
        }
        for(int idx=t; idx<32*64; idx+=256){
            int ic = idx & 31, o = idx >> 5;
            wsm[ic][o] = W[(oh*64+o)*IC + cc*32 + ic];
        }
        __syncthreads();
        for(int ic=0; ic<32; ic++){
            float fv = insm[ic][t];
            unsigned long long xx = pk2(fv,fv);
            const ulonglong2* wr = reinterpret_cast<const ulonglong2*>(&wsm[ic][0]);
            #pragma unroll
            for(int q=0;q<16;q++){
                ulonglong2 w2 = wr[q];
                acc[2*q]   = ffma2(xx, w2.x, acc[2*q]);
                acc[2*q+1] = ffma2(xx, w2.y, acc[2*q+1]);
            }
        }
    }
    #pragma unroll
    for(int q=0;q<32;q++){
        float2 p = upk2(acc[q]);
        int o = 2*q;
        out[o*LP + l]     = p.x + bias[oh*64+o];
        out[(o+1)*LP + l] = p.y + bias[oh*64+o+1];
    }
}

// ---------------- launch ----------------
extern "C" void kernel_launch(void* const* d_in, const int* in_sizes, int n_in,
                              void* d_out, int out_size){
    (void)in_sizes; (void)n_in; (void)out_size;
    const float* x   = (const float*)d_in[0];
    const float* W5a = (const float*)d_in[1];
    const float* g5a = (const float*)d_in[2];
    const float* b5a = (const float*)d_in[3];
    const float* W5c = (const float*)d_in[4];
    const float* g5c = (const float*)d_in[5];
    const float* b5c = (const float*)d_in[6];
    const float* Wq  = (const float*)d_in[7];
    const float* bq  = (const float*)d_in[8];
    const float* Wk  = (const float*)d_in[9];
    const float* bk  = (const float*)d_in[10];
    const float* Wv  = (const float*)d_in[11];
    const float* bv  = (const float*)d_in[12];
    const float* gpam= (const float*)d_in[13];
    const float* gcam= (const float*)d_in[14];
    const float* W51 = (const float*)d_in[15];
    const float* g51 = (const float*)d_in[16];
    const float* b51 = (const float*)d_in[17];
    const float* W52 = (const float*)d_in[18];
    const float* g52 = (const float*)d_in[19];
    const float* b52 = (const float*)d_in[20];
    const float* W6  = (const float*)d_in[21];
    const float* b6  = (const float*)d_in[22];
    const float* W7  = (const float*)d_in[23];
    const float* b7  = (const float*)d_in[24];
    const float* W8  = (const float*)d_in[25];
    const float* b8  = (const float*)d_in[26];
    float* out = (float*)d_out;

    const int c3smem = (C3_INSZ + 3*64*C3_ISTRIDE)*4;   // 97888 B
    static int attr_set = 0;
    if(!attr_set){
        cudaFuncSetAttribute(k_conv3, cudaFuncAttributeMaxDynamicSharedMemorySize, c3smem);
        attr_set = 1;
    }

    k_conv1<<<dim3(8,8,4),256>>>(x, W5a, W5c);
    k_bnstats<<<dim3(128,4),256>>>(0, 1);
    k_bnapply<<<2048,256>>>(0, 1, g5a,b5a,g5c,b5c);

    k_stageA<<<448,256>>>(Wq,bq,Wk,bk,Wv,bv);
    k_stageB<<<640,256>>>();
    k_stageC<<<384,256>>>(gpam,gcam);

    k_conv3<<<dim3(16,8,2),256,c3smem>>>(W51,W52);
    k_bnstats<<<dim3(128,4),256>>>(1, 0);
    k_bnapply<<<2048,256>>>(1, 0, g51,b51,g52,b52);

    k_outconv<<<257,256>>>(W6,b6,W7,b7,W8,b8,out);
}